// round 5
// baseline (speedup 1.0000x reference)
#include <cuda_runtime.h>
#include <math_constants.h>

#define NT   32
#define NA   64
#define NB   64
#define NGEO 128
#define N_ELEM   (NT * NA * NB * NGEO)   // 2^24
#define PLANE    N_ELEM
#define FRAME_SH 19                      // NA*NB*NGEO = 2^19
#define SCALE    10.0f
#define IDX_K    (63.0f / 20.0f)

#define TWO_PI_HI  6.2831854820251465f
#define TWO_PI_LO  (-1.7484556000744083e-7f)
#define INV_2PI    0.15915493667125702f

// Full 2x2x2 neighborhood per cell, packed as TWO adjacent float4s (32B, one
// L1 line per gather pair):
//   scratch8[idx*2 + 0] = { c000, c001, c010, c011 }   (ix plane)
//   scratch8[idx*2 + 1] = { c100, c101, c110, c111 }   (ix+1 plane)
// cval-0 padded at all +1 edges.  64^3 * 32B = 8 MB (L2-resident).
__device__ float4 g_scratch8[64 * 64 * 64 * 2];

// Vectorized build: each thread produces 4 consecutive-iz cells (128B store).
__global__ void __launch_bounds__(256)
build_scratch_kernel(const float* __restrict__ g) {
    int tid = blockIdx.x * blockDim.x + threadIdx.x;   // 0 .. 64^3/4 - 1
    int i   = tid << 2;                                // linear cell index, iz0 % 4 == 0
    int iz0 = i & 63;
    int iy  = (i >> 6) & 63;
    int ix  = i >> 12;
    bool ztail = (iz0 + 4 < 64);

    float r00[5] = {0, 0, 0, 0, 0};
    float r01[5] = {0, 0, 0, 0, 0};
    float r10[5] = {0, 0, 0, 0, 0};
    float r11[5] = {0, 0, 0, 0, 0};

    {   // row (ix, iy)
        float4 a = __ldg(reinterpret_cast<const float4*>(g + i));
        r00[0] = a.x; r00[1] = a.y; r00[2] = a.z; r00[3] = a.w;
        r00[4] = ztail ? __ldg(g + i + 4) : 0.0f;
    }
    if (iy < 63) {   // row (ix, iy+1)
        float4 a = __ldg(reinterpret_cast<const float4*>(g + i + 64));
        r01[0] = a.x; r01[1] = a.y; r01[2] = a.z; r01[3] = a.w;
        r01[4] = ztail ? __ldg(g + i + 68) : 0.0f;
    }
    if (ix < 63) {   // row (ix+1, iy)
        float4 a = __ldg(reinterpret_cast<const float4*>(g + i + 4096));
        r10[0] = a.x; r10[1] = a.y; r10[2] = a.z; r10[3] = a.w;
        r10[4] = ztail ? __ldg(g + i + 4100) : 0.0f;
        if (iy < 63) {   // row (ix+1, iy+1)
            float4 b = __ldg(reinterpret_cast<const float4*>(g + i + 4160));
            r11[0] = b.x; r11[1] = b.y; r11[2] = b.z; r11[3] = b.w;
            r11[4] = ztail ? __ldg(g + i + 4164) : 0.0f;
        }
    }

#pragma unroll
    for (int k = 0; k < 4; k++) {
        bool zedge = (iz0 + k == 63);
        g_scratch8[(i + k) * 2 + 0] = make_float4(r00[k], zedge ? 0.f : r00[k + 1],
                                                  r01[k], zedge ? 0.f : r01[k + 1]);
        g_scratch8[(i + k) * 2 + 1] = make_float4(r10[k], zedge ? 0.f : r10[k + 1],
                                                  r11[k], zedge ? 0.f : r11[k + 1]);
    }
}

__global__ void __launch_bounds__(128)
grid_predictor_kernel(const float* __restrict__ t_frames,
                      const float* __restrict__ coords,
                      const float* __restrict__ Omega,
                      const float* __restrict__ t_geos,
                      const float* __restrict__ t_injection,
                      const float* __restrict__ t_start_obs,
                      float* __restrict__ out) {
    int gid  = blockIdx.x * blockDim.x + threadIdx.x;   // vec4 index
    int base = gid << 2;

    int t = base >> FRAME_SH;
    float tM   = __ldg(t_frames + t) - __ldg(t_start_obs);
    float tinj = __ldg(t_injection);

    float4 tg = __ldcs(reinterpret_cast<const float4*>(t_geos + base));
    float4 om = __ldcs(reinterpret_cast<const float4*>(Omega  + base));
    float4 xv = __ldcs(reinterpret_cast<const float4*>(coords + base));
    float4 yv = __ldcs(reinterpret_cast<const float4*>(coords + PLANE + base));
    float4 zv = __ldcs(reinterpret_cast<const float4*>(coords + 2 * PLANE + base));

    const float* tgp = reinterpret_cast<const float*>(&tg);
    const float* omp = reinterpret_cast<const float*>(&om);
    const float* xp  = reinterpret_cast<const float*>(&xv);
    const float* yp  = reinterpret_cast<const float*>(&yv);
    const float* zp  = reinterpret_cast<const float*>(&zv);

    // ---- phase 1: offsets + weights ----
    int   offA[4];
    float wxa[4], wya[4], wza[4];
    bool  okj[4];
#pragma unroll
    for (int j = 0; j < 4; j++) {
        float trot = tM - tgp[j] - tinj;
        float x = xp[j], y = yp[j], z = zp[j];
        float r2 = fmaf(x, x, fmaf(y, y, z * z));
        bool ok = (trot >= 0.0f) && (r2 >= 4.0f) && (r2 <= 100.0f)
                  && (fabsf(z) <= 4.0f);
        okj[j] = ok;

        float theta = -omp[j] * trot;
        float k = rintf(theta * INV_2PI);
        float th = fmaf(-k, TWO_PI_HI, theta);
        th = fmaf(-k, TWO_PI_LO, th);
        float s, c;
        __sincosf(th, &s, &c);

        float xw = x * c - y * s;
        float yw = x * s + y * c;

        float gx = (xw + SCALE) * IDX_K;
        float gy = (yw + SCALE) * IDX_K;
        float gz = (z  + SCALE) * IDX_K;

        int ix = min(max(__float2int_rd(gx), 0), 62);
        int iy = min(max(__float2int_rd(gy), 0), 62);
        int iz = min(max(__float2int_rd(gz), 0), 63);
        wxa[j] = gx - (float)ix;
        wya[j] = gy - (float)iy;
        wza[j] = gz - (float)iz;

        // invalid lanes -> cell 0 (broadcast line)
        offA[j] = ok ? (((ix << 12) | (iy << 6) | iz) << 1) : 0;
    }

    // ---- phase 2: 8 gathers, each A/B pair shares one 128B line ----
    float4 A0 = __ldg(&g_scratch8[offA[0]]);
    float4 B0 = __ldg(&g_scratch8[offA[0] + 1]);
    float4 A1 = __ldg(&g_scratch8[offA[1]]);
    float4 B1 = __ldg(&g_scratch8[offA[1] + 1]);
    float4 A2 = __ldg(&g_scratch8[offA[2]]);
    float4 B2 = __ldg(&g_scratch8[offA[2] + 1]);
    float4 A3 = __ldg(&g_scratch8[offA[3]]);
    float4 B3 = __ldg(&g_scratch8[offA[3] + 1]);

    // ---- phase 3: lerp + sigmoid + mask ----
    float4 res;
    float* rp = reinterpret_cast<float*>(&res);
    float4 Aj[4] = {A0, A1, A2, A3};
    float4 Bj[4] = {B0, B1, B2, B3};
#pragma unroll
    for (int j = 0; j < 4; j++) {
        float wz = wza[j], wy = wya[j], wx = wxa[j];
        float4 A = Aj[j], B = Bj[j];
        float v00 = A.x + wz * (A.y - A.x);
        float v01 = A.z + wz * (A.w - A.z);
        float v10 = B.x + wz * (B.y - B.x);
        float v11 = B.z + wz * (B.w - B.z);
        float v0  = v00 + wy * (v01 - v00);
        float v1  = v10 + wy * (v11 - v10);
        float v   = v0 + wx * (v1 - v0);
        float e   = __fdividef(1.0f, 1.0f + __expf(10.0f - v));
        rp[j] = okj[j] ? e : 0.0f;
    }

    __stcs(reinterpret_cast<float4*>(out + base), res);
}

extern "C" void kernel_launch(void* const* d_in, const int* in_sizes, int n_in,
                              void* d_out, int out_size) {
    const float* t_frames    = (const float*)d_in[0];
    const float* coords      = (const float*)d_in[1];
    const float* Omega       = (const float*)d_in[2];
    const float* t_geos      = (const float*)d_in[3];
    const float* t_injection = (const float*)d_in[4];
    const float* t_start_obs = (const float*)d_in[5];
    const float* grid        = (const float*)d_in[6];
    float* out               = (float*)d_out;

    build_scratch_kernel<<<(64 * 64 * 64 / 4) / 256, 256>>>(grid);

    int nvec  = N_ELEM / 4;
    int block = 128;
    int nblk  = nvec / block;
    grid_predictor_kernel<<<nblk, block>>>(t_frames, coords, Omega, t_geos,
                                           t_injection, t_start_obs, out);
}

// round 6
// speedup vs baseline: 1.0004x; 1.0004x over previous
#include <cuda_runtime.h>
#include <math_constants.h>

#define NT   32
#define NA   64
#define NB   64
#define NGEO 128
#define N_ELEM   (NT * NA * NB * NGEO)   // 2^24
#define PLANE    N_ELEM
#define FRAME_SH 19                      // NA*NB*NGEO = 2^19
#define SCALE    10.0f
#define IDX_K    (63.0f / 20.0f)

#define TWO_PI_HI  6.2831854820251465f
#define TWO_PI_LO  (-1.7484556000744083e-7f)
#define INV_2PI    0.15915493667125702f

// Full 2x2x2 neighborhood per cell, packed as 32B (one LDG.256 per gather):
//   [0..3] = { c000, c001, c010, c011 }   (ix plane)
//   [4..7] = { c100, c101, c110, c111 }   (ix+1 plane)
// cval-0 padded at +1 edges. 64^3 * 32B = 8 MB (L2-resident). 32B-aligned.
__device__ __align__(32) float4 g_scratch8[64 * 64 * 64 * 2];

// Vectorized build: each thread produces 4 consecutive-iz cells.
__global__ void __launch_bounds__(256)
build_scratch_kernel(const float* __restrict__ g) {
    int tid = blockIdx.x * blockDim.x + threadIdx.x;   // 0 .. 64^3/4 - 1
    int i   = tid << 2;                                // linear cell index, iz0 % 4 == 0
    int iz0 = i & 63;
    int iy  = (i >> 6) & 63;
    int ix  = i >> 12;
    bool ztail = (iz0 + 4 < 64);

    float r00[5] = {0, 0, 0, 0, 0};
    float r01[5] = {0, 0, 0, 0, 0};
    float r10[5] = {0, 0, 0, 0, 0};
    float r11[5] = {0, 0, 0, 0, 0};

    {   // row (ix, iy)
        float4 a = __ldg(reinterpret_cast<const float4*>(g + i));
        r00[0] = a.x; r00[1] = a.y; r00[2] = a.z; r00[3] = a.w;
        r00[4] = ztail ? __ldg(g + i + 4) : 0.0f;
    }
    if (iy < 63) {   // row (ix, iy+1)
        float4 a = __ldg(reinterpret_cast<const float4*>(g + i + 64));
        r01[0] = a.x; r01[1] = a.y; r01[2] = a.z; r01[3] = a.w;
        r01[4] = ztail ? __ldg(g + i + 68) : 0.0f;
    }
    if (ix < 63) {   // row (ix+1, iy)
        float4 a = __ldg(reinterpret_cast<const float4*>(g + i + 4096));
        r10[0] = a.x; r10[1] = a.y; r10[2] = a.z; r10[3] = a.w;
        r10[4] = ztail ? __ldg(g + i + 4100) : 0.0f;
        if (iy < 63) {   // row (ix+1, iy+1)
            float4 b = __ldg(reinterpret_cast<const float4*>(g + i + 4160));
            r11[0] = b.x; r11[1] = b.y; r11[2] = b.z; r11[3] = b.w;
            r11[4] = ztail ? __ldg(g + i + 4164) : 0.0f;
        }
    }

#pragma unroll
    for (int k = 0; k < 4; k++) {
        bool zedge = (iz0 + k == 63);
        g_scratch8[(i + k) * 2 + 0] = make_float4(r00[k], zedge ? 0.f : r00[k + 1],
                                                  r01[k], zedge ? 0.f : r01[k + 1]);
        g_scratch8[(i + k) * 2 + 1] = make_float4(r10[k], zedge ? 0.f : r10[k + 1],
                                                  r11[k], zedge ? 0.f : r11[k + 1]);
    }
}

// 256-bit gather: 8 corners in one instruction (sm_100a).
__device__ __forceinline__ void ldg256(const float4* p, float c[8]) {
    asm volatile("ld.global.nc.v8.f32 {%0,%1,%2,%3,%4,%5,%6,%7}, [%8];"
                 : "=f"(c[0]), "=f"(c[1]), "=f"(c[2]), "=f"(c[3]),
                   "=f"(c[4]), "=f"(c[5]), "=f"(c[6]), "=f"(c[7])
                 : "l"(p));
}

__global__ void __launch_bounds__(128)
grid_predictor_kernel(const float* __restrict__ t_frames,
                      const float* __restrict__ coords,
                      const float* __restrict__ Omega,
                      const float* __restrict__ t_geos,
                      const float* __restrict__ t_injection,
                      const float* __restrict__ t_start_obs,
                      float* __restrict__ out) {
    int gid  = blockIdx.x * blockDim.x + threadIdx.x;   // vec4 index
    int base = gid << 2;

    int t = base >> FRAME_SH;
    float tM   = __ldg(t_frames + t) - __ldg(t_start_obs);
    float tinj = __ldg(t_injection);

    float4 tg = __ldcs(reinterpret_cast<const float4*>(t_geos + base));
    float4 om = __ldcs(reinterpret_cast<const float4*>(Omega  + base));
    float4 xv = __ldcs(reinterpret_cast<const float4*>(coords + base));
    float4 yv = __ldcs(reinterpret_cast<const float4*>(coords + PLANE + base));
    float4 zv = __ldcs(reinterpret_cast<const float4*>(coords + 2 * PLANE + base));

    const float* tgp = reinterpret_cast<const float*>(&tg);
    const float* omp = reinterpret_cast<const float*>(&om);
    const float* xp  = reinterpret_cast<const float*>(&xv);
    const float* yp  = reinterpret_cast<const float*>(&yv);
    const float* zp  = reinterpret_cast<const float*>(&zv);

    // ---- phase 1: offsets + weights ----
    int   offA[4];
    float wxa[4], wya[4], wza[4];
    bool  okj[4];
#pragma unroll
    for (int j = 0; j < 4; j++) {
        float trot = tM - tgp[j] - tinj;
        float x = xp[j], y = yp[j], z = zp[j];
        float r2 = fmaf(x, x, fmaf(y, y, z * z));
        bool ok = (trot >= 0.0f) && (r2 >= 4.0f) && (r2 <= 100.0f)
                  && (fabsf(z) <= 4.0f);
        okj[j] = ok;

        float theta = -omp[j] * trot;
        float k = rintf(theta * INV_2PI);
        float th = fmaf(-k, TWO_PI_HI, theta);
        th = fmaf(-k, TWO_PI_LO, th);
        float s, c;
        __sincosf(th, &s, &c);

        float xw = x * c - y * s;
        float yw = x * s + y * c;

        float gx = (xw + SCALE) * IDX_K;
        float gy = (yw + SCALE) * IDX_K;
        float gz = (z  + SCALE) * IDX_K;

        int ix = min(max(__float2int_rd(gx), 0), 62);
        int iy = min(max(__float2int_rd(gy), 0), 62);
        int iz = min(max(__float2int_rd(gz), 0), 63);
        wxa[j] = gx - (float)ix;
        wya[j] = gy - (float)iy;
        wza[j] = gz - (float)iz;

        offA[j] = ((ix << 12) | (iy << 6) | iz) << 1;
    }

    // ---- phase 2: one predicated 256-bit gather per element ----
    float C0[8] = {0, 0, 0, 0, 0, 0, 0, 0};
    float C1[8] = {0, 0, 0, 0, 0, 0, 0, 0};
    float C2[8] = {0, 0, 0, 0, 0, 0, 0, 0};
    float C3[8] = {0, 0, 0, 0, 0, 0, 0, 0};
    if (okj[0]) ldg256(&g_scratch8[offA[0]], C0);
    if (okj[1]) ldg256(&g_scratch8[offA[1]], C1);
    if (okj[2]) ldg256(&g_scratch8[offA[2]], C2);
    if (okj[3]) ldg256(&g_scratch8[offA[3]], C3);

    // ---- phase 3: lerp + sigmoid + mask ----
    float4 res;
    float* rp = reinterpret_cast<float*>(&res);
    const float* Cj[4] = {C0, C1, C2, C3};
#pragma unroll
    for (int j = 0; j < 4; j++) {
        float wz = wza[j], wy = wya[j], wx = wxa[j];
        const float* C = Cj[j];
        float v00 = C[0] + wz * (C[1] - C[0]);
        float v01 = C[2] + wz * (C[3] - C[2]);
        float v10 = C[4] + wz * (C[5] - C[4]);
        float v11 = C[6] + wz * (C[7] - C[6]);
        float v0  = v00 + wy * (v01 - v00);
        float v1  = v10 + wy * (v11 - v10);
        float v   = v0 + wx * (v1 - v0);
        float e   = __fdividef(1.0f, 1.0f + __expf(10.0f - v));
        rp[j] = okj[j] ? e : 0.0f;
    }

    __stcs(reinterpret_cast<float4*>(out + base), res);
}

extern "C" void kernel_launch(void* const* d_in, const int* in_sizes, int n_in,
                              void* d_out, int out_size) {
    const float* t_frames    = (const float*)d_in[0];
    const float* coords      = (const float*)d_in[1];
    const float* Omega       = (const float*)d_in[2];
    const float* t_geos      = (const float*)d_in[3];
    const float* t_injection = (const float*)d_in[4];
    const float* t_start_obs = (const float*)d_in[5];
    const float* grid        = (const float*)d_in[6];
    float* out               = (float*)d_out;

    build_scratch_kernel<<<(64 * 64 * 64 / 4) / 256, 256>>>(grid);

    int nvec  = N_ELEM / 4;
    int block = 128;
    int nblk  = nvec / block;
    grid_predictor_kernel<<<nblk, block>>>(t_frames, coords, Omega, t_geos,
                                           t_injection, t_start_obs, out);
}

// round 7
// speedup vs baseline: 1.0404x; 1.0399x over previous
#include <cuda_runtime.h>
#include <math_constants.h>

#define NT   32
#define NA   64
#define NB   64
#define NGEO 128
#define N_ELEM   (NT * NA * NB * NGEO)   // 2^24
#define PLANE    N_ELEM
#define FRAME_SH 19                      // NA*NB*NGEO = 2^19
#define SCALE    10.0f
#define IDX_K    (63.0f / 20.0f)

#define TWO_PI_HI  6.2831854820251465f
#define TWO_PI_LO  (-1.7484556000744083e-7f)
#define INV_2PI    0.15915493667125702f

// Full 2x2x2 neighborhood per cell, packed as 32B (one LDG.256 per gather):
//   [0..3] = { c000, c001, c010, c011 }   (ix plane)
//   [4..7] = { c100, c101, c110, c111 }   (ix+1 plane)
// Only cells with iz in [16,47] are built: valid queries have gz in [18.9,44.1]
// (|z|<=4), so iz in [18,44]. Unbuilt cells are never loaded (predicated gather).
__device__ __align__(32) float4 g_scratch8[64 * 64 * 64 * 2];

// Build kernel over the reachable z-band only: iz0 in {16,20,...,44} (8 groups).
// Each thread produces 4 consecutive-iz cells.
__global__ void __launch_bounds__(256)
build_scratch_kernel(const float* __restrict__ g) {
    int tid = blockIdx.x * blockDim.x + threadIdx.x;   // 0 .. 64*64*8 - 1
    int zg  = tid & 7;                                 // z-group: iz0 = 16 + 4*zg
    int yx  = tid >> 3;                                // (ix<<6)|iy
    int i   = (yx << 6) | (16 + (zg << 2));            // linear cell index
    int iz0 = i & 63;
    int iy  = (i >> 6) & 63;
    int ix  = i >> 12;
    bool ztail = (iz0 + 4 < 64);

    float r00[5] = {0, 0, 0, 0, 0};
    float r01[5] = {0, 0, 0, 0, 0};
    float r10[5] = {0, 0, 0, 0, 0};
    float r11[5] = {0, 0, 0, 0, 0};

    {   // row (ix, iy)
        float4 a = __ldg(reinterpret_cast<const float4*>(g + i));
        r00[0] = a.x; r00[1] = a.y; r00[2] = a.z; r00[3] = a.w;
        r00[4] = ztail ? __ldg(g + i + 4) : 0.0f;
    }
    if (iy < 63) {   // row (ix, iy+1)
        float4 a = __ldg(reinterpret_cast<const float4*>(g + i + 64));
        r01[0] = a.x; r01[1] = a.y; r01[2] = a.z; r01[3] = a.w;
        r01[4] = ztail ? __ldg(g + i + 68) : 0.0f;
    }
    if (ix < 63) {   // row (ix+1, iy)
        float4 a = __ldg(reinterpret_cast<const float4*>(g + i + 4096));
        r10[0] = a.x; r10[1] = a.y; r10[2] = a.z; r10[3] = a.w;
        r10[4] = ztail ? __ldg(g + i + 4100) : 0.0f;
        if (iy < 63) {   // row (ix+1, iy+1)
            float4 b = __ldg(reinterpret_cast<const float4*>(g + i + 4160));
            r11[0] = b.x; r11[1] = b.y; r11[2] = b.z; r11[3] = b.w;
            r11[4] = ztail ? __ldg(g + i + 4164) : 0.0f;
        }
    }

#pragma unroll
    for (int k = 0; k < 4; k++) {
        bool zedge = (iz0 + k == 63);
        g_scratch8[(i + k) * 2 + 0] = make_float4(r00[k], zedge ? 0.f : r00[k + 1],
                                                  r01[k], zedge ? 0.f : r01[k + 1]);
        g_scratch8[(i + k) * 2 + 1] = make_float4(r10[k], zedge ? 0.f : r10[k + 1],
                                                  r11[k], zedge ? 0.f : r11[k + 1]);
    }
}

// Predicated 256-bit gather: no BSSY/BSYNC envelope, zeros when !ok.
__device__ __forceinline__ void ldg256_pred(const float4* p, bool ok, float c[8]) {
    unsigned pr = ok ? 1u : 0u;
    asm volatile(
        "{\n\t"
        ".reg .pred p;\n\t"
        "setp.ne.u32 p, %9, 0;\n\t"
        "mov.f32 %0, 0f00000000;\n\t"
        "mov.f32 %1, 0f00000000;\n\t"
        "mov.f32 %2, 0f00000000;\n\t"
        "mov.f32 %3, 0f00000000;\n\t"
        "mov.f32 %4, 0f00000000;\n\t"
        "mov.f32 %5, 0f00000000;\n\t"
        "mov.f32 %6, 0f00000000;\n\t"
        "mov.f32 %7, 0f00000000;\n\t"
        "@p ld.global.nc.v8.f32 {%0,%1,%2,%3,%4,%5,%6,%7}, [%8];\n\t"
        "}"
        : "=f"(c[0]), "=f"(c[1]), "=f"(c[2]), "=f"(c[3]),
          "=f"(c[4]), "=f"(c[5]), "=f"(c[6]), "=f"(c[7])
        : "l"(p), "r"(pr));
}

__global__ void __launch_bounds__(128)
grid_predictor_kernel(const float* __restrict__ t_frames,
                      const float* __restrict__ coords,
                      const float* __restrict__ Omega,
                      const float* __restrict__ t_geos,
                      const float* __restrict__ t_injection,
                      const float* __restrict__ t_start_obs,
                      float* __restrict__ out) {
    int gid  = blockIdx.x * blockDim.x + threadIdx.x;   // vec4 index
    int base = gid << 2;

    int t = base >> FRAME_SH;
    float tM   = __ldg(t_frames + t) - __ldg(t_start_obs);
    float tinj = __ldg(t_injection);

    float4 tg = __ldcs(reinterpret_cast<const float4*>(t_geos + base));
    float4 om = __ldcs(reinterpret_cast<const float4*>(Omega  + base));
    float4 xv = __ldcs(reinterpret_cast<const float4*>(coords + base));
    float4 yv = __ldcs(reinterpret_cast<const float4*>(coords + PLANE + base));
    float4 zv = __ldcs(reinterpret_cast<const float4*>(coords + 2 * PLANE + base));

    const float* tgp = reinterpret_cast<const float*>(&tg);
    const float* omp = reinterpret_cast<const float*>(&om);
    const float* xp  = reinterpret_cast<const float*>(&xv);
    const float* yp  = reinterpret_cast<const float*>(&yv);
    const float* zp  = reinterpret_cast<const float*>(&zv);

    // ---- phase 1: offsets + weights ----
    int   offA[4];
    float wxa[4], wya[4], wza[4];
    bool  okj[4];
#pragma unroll
    for (int j = 0; j < 4; j++) {
        float trot = tM - tgp[j] - tinj;
        float x = xp[j], y = yp[j], z = zp[j];
        float r2 = fmaf(x, x, fmaf(y, y, z * z));
        bool ok = (trot >= 0.0f) && (r2 >= 4.0f) && (r2 <= 100.0f)
                  && (fabsf(z) <= 4.0f);
        okj[j] = ok;

        float theta = -omp[j] * trot;
        float k = rintf(theta * INV_2PI);
        float th = fmaf(-k, TWO_PI_HI, theta);
        th = fmaf(-k, TWO_PI_LO, th);
        float s, c;
        __sincosf(th, &s, &c);

        float xw = x * c - y * s;
        float yw = x * s + y * c;

        float gx = (xw + SCALE) * IDX_K;
        float gy = (yw + SCALE) * IDX_K;
        float gz = (z  + SCALE) * IDX_K;

        int ix = min(max(__float2int_rd(gx), 0), 62);
        int iy = min(max(__float2int_rd(gy), 0), 62);
        int iz = min(max(__float2int_rd(gz), 0), 63);
        wxa[j] = gx - (float)ix;
        wya[j] = gy - (float)iy;
        wza[j] = gz - (float)iz;

        offA[j] = ((ix << 12) | (iy << 6) | iz) << 1;
    }

    // ---- phase 2: predicated 256-bit gathers, no branch envelopes ----
    float C0[8], C1[8], C2[8], C3[8];
    ldg256_pred(&g_scratch8[offA[0]], okj[0], C0);
    ldg256_pred(&g_scratch8[offA[1]], okj[1], C1);
    ldg256_pred(&g_scratch8[offA[2]], okj[2], C2);
    ldg256_pred(&g_scratch8[offA[3]], okj[3], C3);

    // ---- phase 3: lerp + sigmoid + mask ----
    float4 res;
    float* rp = reinterpret_cast<float*>(&res);
    const float* Cj[4] = {C0, C1, C2, C3};
#pragma unroll
    for (int j = 0; j < 4; j++) {
        float wz = wza[j], wy = wya[j], wx = wxa[j];
        const float* C = Cj[j];
        float v00 = C[0] + wz * (C[1] - C[0]);
        float v01 = C[2] + wz * (C[3] - C[2]);
        float v10 = C[4] + wz * (C[5] - C[4]);
        float v11 = C[6] + wz * (C[7] - C[6]);
        float v0  = v00 + wy * (v01 - v00);
        float v1  = v10 + wy * (v11 - v10);
        float v   = v0 + wx * (v1 - v0);
        float e   = __fdividef(1.0f, 1.0f + __expf(10.0f - v));
        rp[j] = okj[j] ? e : 0.0f;
    }

    __stcs(reinterpret_cast<float4*>(out + base), res);
}

extern "C" void kernel_launch(void* const* d_in, const int* in_sizes, int n_in,
                              void* d_out, int out_size) {
    const float* t_frames    = (const float*)d_in[0];
    const float* coords      = (const float*)d_in[1];
    const float* Omega       = (const float*)d_in[2];
    const float* t_geos      = (const float*)d_in[3];
    const float* t_injection = (const float*)d_in[4];
    const float* t_start_obs = (const float*)d_in[5];
    const float* grid        = (const float*)d_in[6];
    float* out               = (float*)d_out;

    // Build only the reachable z-band: 64*64*8 threads (4 cells each).
    build_scratch_kernel<<<(64 * 64 * 8) / 256, 256>>>(grid);

    int nvec  = N_ELEM / 4;
    int block = 128;
    int nblk  = nvec / block;
    grid_predictor_kernel<<<nblk, block>>>(t_frames, coords, Omega, t_geos,
                                           t_injection, t_start_obs, out);
}